// round 4
// baseline (speedup 1.0000x reference)
#include <cuda_runtime.h>
#include <cstdint>
#include <cstddef>

#define T_STEPS 32768
#define CD 512
#define ID 1024
#define NG 2048

// ---------------- device-global scratch ------------------------------------
__device__ float g_gx[(size_t)T_STEPS * NG];        // precomputed Wx@x + b, [T][2048]
__device__ unsigned long long g_hpub[2 * CD];       // (h float bits) | (step tag << 32), double buffered

// ---------------- morally-strong 8B accessors (PTX memory model) ------------
__device__ __forceinline__ unsigned long long ld_acq64(const unsigned long long* p) {
    unsigned long long v;
    asm volatile("ld.acquire.gpu.global.b64 %0, [%1];" : "=l"(v) : "l"(p) : "memory");
    return v;
}
__device__ __forceinline__ void st_rel64(unsigned long long* p, unsigned long long v) {
    asm volatile("st.release.gpu.global.b64 [%0], %1;" :: "l"(p), "l"(v) : "memory");
}

// ---------------- init (reset published-h tags every replay) ----------------
__global__ void init_kernel() {
    int i = threadIdx.x;
    if (i < 2 * CD) g_hpub[i] = 0ull;   // h = 0.0f, tag = 0
}

// ---------------- GEMM: g_gx[t][r] = sum_k x[t][k]*W[r][k] + b[r] -----------
// C = x[32768,512] * W[2048,512]^T, 128x128x8 tiles, 8x8 microtile.
#define GBM 128
#define GBN 128
#define GBK 8

__global__ __launch_bounds__(256) void gemm_gx_kernel(
    const float* __restrict__ x,
    const float* __restrict__ wf_w, const float* __restrict__ wf_b,
    const float* __restrict__ wi_w, const float* __restrict__ wi_b,
    const float* __restrict__ wc_w, const float* __restrict__ wc_b,
    const float* __restrict__ wo_w, const float* __restrict__ wo_b)
{
    __shared__ float As[GBK][GBM];
    __shared__ float Bs[GBK][GBN];

    const int tid = threadIdx.x;
    const int tx = tid & 15;        // output col group
    const int ty = tid >> 4;        // output row group
    const int r0 = blockIdx.x * GBN;
    const int t0 = blockIdx.y * GBM;
    const int gate = r0 >> 9;       // 128 | 512 -> gate constant per block
    const int rbase = r0 & 511;

    const float* wsrc = (gate == 0) ? wf_w : (gate == 1) ? wi_w : (gate == 2) ? wc_w : wo_w;
    const float* bsrc = (gate == 0) ? wf_b : (gate == 1) ? wi_b : (gate == 2) ? wc_b : wo_b;

    const int lrow = tid >> 1;          // 0..127
    const int lk4  = (tid & 1) * 4;     // 0 or 4

    float acc[8][8];
    #pragma unroll
    for (int i = 0; i < 8; i++)
        #pragma unroll
        for (int j = 0; j < 8; j++) acc[i][j] = 0.0f;

    for (int k0 = 0; k0 < CD; k0 += GBK) {
        float4 av = *(const float4*)(x    + (size_t)(t0 + lrow) * CD + k0 + lk4);
        float4 bv = *(const float4*)(wsrc + (size_t)(rbase + lrow) * ID + k0 + lk4);
        __syncthreads();
        As[lk4 + 0][lrow] = av.x; As[lk4 + 1][lrow] = av.y;
        As[lk4 + 2][lrow] = av.z; As[lk4 + 3][lrow] = av.w;
        Bs[lk4 + 0][lrow] = bv.x; Bs[lk4 + 1][lrow] = bv.y;
        Bs[lk4 + 2][lrow] = bv.z; Bs[lk4 + 3][lrow] = bv.w;
        __syncthreads();
        #pragma unroll
        for (int k = 0; k < GBK; k++) {
            const float4* As4 = (const float4*)As[k];
            const float4* Bs4 = (const float4*)Bs[k];
            float4 a0 = As4[ty], a1 = As4[16 + ty];
            float4 b0 = Bs4[tx], b1 = Bs4[16 + tx];
            float ar[8] = {a0.x, a0.y, a0.z, a0.w, a1.x, a1.y, a1.z, a1.w};
            float br[8] = {b0.x, b0.y, b0.z, b0.w, b1.x, b1.y, b1.z, b1.w};
            #pragma unroll
            for (int i = 0; i < 8; i++)
                #pragma unroll
                for (int j = 0; j < 8; j++) acc[i][j] += ar[i] * br[j];
        }
    }

    float4 bias0 = *(const float4*)(bsrc + rbase + tx * 4);
    float4 bias1 = *(const float4*)(bsrc + rbase + 64 + tx * 4);
    float bb[8] = {bias0.x, bias0.y, bias0.z, bias0.w, bias1.x, bias1.y, bias1.z, bias1.w};

    #pragma unroll
    for (int i = 0; i < 8; i++) {
        int trow = t0 + ((i < 4) ? (ty * 4 + i) : (64 + ty * 4 + i - 4));
        float4 o0, o1;
        o0.x = acc[i][0] + bb[0]; o0.y = acc[i][1] + bb[1];
        o0.z = acc[i][2] + bb[2]; o0.w = acc[i][3] + bb[3];
        o1.x = acc[i][4] + bb[4]; o1.y = acc[i][5] + bb[5];
        o1.z = acc[i][6] + bb[6]; o1.w = acc[i][7] + bb[7];
        *(float4*)(g_gx + (size_t)trow * NG + r0 + tx * 4)      = o0;
        *(float4*)(g_gx + (size_t)trow * NG + r0 + 64 + tx * 4) = o1;
    }
}

// ---------------- persistent recurrent kernel --------------------------------
#define NB   64
#define TPB  256
#define JPB  8            // h indices per CTA
#define NROWS 32          // 4 gates * JPB rows per CTA
#define K4   16           // float4 chunks of h per lane: 8 lanes * 16 * 4 = 512

__device__ __forceinline__ float sigmoid_f(float x) {
    return __fdividef(1.0f, 1.0f + __expf(-x));
}
__device__ __forceinline__ float tanh_f(float x) {
    float ax = fabsf(x);
    float e  = __expf(-2.0f * ax);
    float t  = __fdividef(1.0f - e, 1.0f + e);
    return copysignf(t, x);
}

__global__ __launch_bounds__(TPB, 1) void lstm_rec_kernel(
    const float* __restrict__ wf_w, const float* __restrict__ wi_w,
    const float* __restrict__ wc_w, const float* __restrict__ wo_w,
    float* __restrict__ d_out)
{
    __shared__ float4 hs4[CD / 4];     // h(t) broadcast, 128 float4
    __shared__ float gsm[NROWS];
    float* hsf = (float*)hs4;

    const int tid  = threadIdx.x;
    const int r    = tid >> 3;          // local row 0..31
    const int c    = tid & 7;           // lane within row
    const int gate = r >> 3;
    const int jj   = r & 7;
    const int j0   = blockIdx.x * JPB;

    // ---- this thread's 64 h-part weights in registers (16 float4)
    const float* wsrc = (gate == 0) ? wf_w : (gate == 1) ? wi_w : (gate == 2) ? wc_w : wo_w;
    const float4* wp = (const float4*)(wsrc + (size_t)(j0 + jj) * ID + CD);
    float4 wv[K4];
    #pragma unroll
    for (int kk = 0; kk < K4; kk++) wv[kk] = wp[c + 8 * kk];

    // ---- gx (x-part) registers for the JPB owner threads
    const bool owner = (tid < JPB);
    const float* gxp = g_gx + j0 + tid;   // + t*NG + gate*CD
    float gxf = 0.f, gxi = 0.f, gxc = 0.f, gxo = 0.f;
    if (owner) {
        gxf = __ldcs(gxp);
        gxi = __ldcs(gxp + CD);
        gxc = __ldcs(gxp + 2 * CD);
        gxo = __ldcs(gxp + 3 * CD);
    }

    float c_state = 0.0f;
    float h_last  = 0.0f;

    for (int t = 0; t < T_STEPS; t++) {
        // ---- wait for h(t): acquire-poll published 8B words (tag in high half)
        unsigned long long* hb = g_hpub + (size_t)(t & 1) * CD;
        unsigned long long v0 = ld_acq64(hb + 2 * tid);
        while ((unsigned)(v0 >> 32) != (unsigned)t) v0 = ld_acq64(hb + 2 * tid);
        unsigned long long v1 = ld_acq64(hb + 2 * tid + 1);
        while ((unsigned)(v1 >> 32) != (unsigned)t) v1 = ld_acq64(hb + 2 * tid + 1);
        hsf[2 * tid]     = __uint_as_float((unsigned)v0);
        hsf[2 * tid + 1] = __uint_as_float((unsigned)v1);
        __syncthreads();

        // ---- prefetch next step's x-part contributions (overlaps the dot)
        float nf = 0.f, ni = 0.f, nc = 0.f, no = 0.f;
        if (owner && (t + 1) < T_STEPS) {
            const float* p = gxp + (size_t)(t + 1) * NG;
            nf = __ldcs(p);
            ni = __ldcs(p + CD);
            nc = __ldcs(p + 2 * CD);
            no = __ldcs(p + 3 * CD);
        }

        // ---- recurrent dot: 64 scalar MACs, 4 accumulators
        float a0 = 0.f, a1 = 0.f, a2 = 0.f, a3 = 0.f;
        #pragma unroll
        for (int kk = 0; kk < K4; kk += 4) {
            float4 h0 = hs4[c + 8 * (kk + 0)];
            float4 h1 = hs4[c + 8 * (kk + 1)];
            float4 h2 = hs4[c + 8 * (kk + 2)];
            float4 h3 = hs4[c + 8 * (kk + 3)];
            a0 += wv[kk + 0].x * h0.x + wv[kk + 0].y * h0.y + wv[kk + 0].z * h0.z + wv[kk + 0].w * h0.w;
            a1 += wv[kk + 1].x * h1.x + wv[kk + 1].y * h1.y + wv[kk + 1].z * h1.z + wv[kk + 1].w * h1.w;
            a2 += wv[kk + 2].x * h2.x + wv[kk + 2].y * h2.y + wv[kk + 2].z * h2.z + wv[kk + 2].w * h2.w;
            a3 += wv[kk + 3].x * h3.x + wv[kk + 3].y * h3.y + wv[kk + 3].z * h3.z + wv[kk + 3].w * h3.w;
        }
        float acc = (a0 + a1) + (a2 + a3);
        acc += __shfl_down_sync(0xffffffffu, acc, 4);
        acc += __shfl_down_sync(0xffffffffu, acc, 2);
        acc += __shfl_down_sync(0xffffffffu, acc, 1);
        if (c == 0) gsm[r] = acc;
        __syncthreads();

        // ---- gate update + release-publish h(t+1) with embedded tag
        if (owner) {
            float gf = gsm[tid]      + gxf;
            float gi = gsm[ 8 + tid] + gxi;
            float gc = gsm[16 + tid] + gxc;
            float go = gsm[24 + tid] + gxo;
            float f  = sigmoid_f(gf);
            float ii = sigmoid_f(gi);
            float cc = tanh_f(gc);
            float oo = sigmoid_f(go);
            c_state = f * c_state + ii * cc;
            h_last  = tanh_f(c_state) * oo;
            unsigned long long pv = (unsigned long long)__float_as_uint(h_last)
                                  | ((unsigned long long)(unsigned)(t + 1) << 32);
            st_rel64(&g_hpub[(size_t)((t + 1) & 1) * CD + j0 + tid], pv);
            gxf = nf; gxi = ni; gxc = nc; gxo = no;
        }
        // next iteration's acquire-poll is the inter-CTA barrier
    }

    if (owner) {
        d_out[j0 + tid]      = c_state;   // output = (c, h)
        d_out[CD + j0 + tid] = h_last;
    }
}

// ---------------- launch -----------------------------------------------------
extern "C" void kernel_launch(void* const* d_in, const int* in_sizes, int n_in,
                              void* d_out, int out_size) {
    (void)in_sizes; (void)n_in; (void)out_size;
    const float* x    = (const float*)d_in[0];
    const float* wf_w = (const float*)d_in[1];
    const float* wf_b = (const float*)d_in[2];
    const float* wi_w = (const float*)d_in[3];
    const float* wi_b = (const float*)d_in[4];
    const float* wc_w = (const float*)d_in[5];
    const float* wc_b = (const float*)d_in[6];
    const float* wo_w = (const float*)d_in[7];
    const float* wo_b = (const float*)d_in[8];
    float* out = (float*)d_out;

    init_kernel<<<1, 1024>>>();

    dim3 ggrid(NG / GBN, T_STEPS / GBM);
    gemm_gx_kernel<<<ggrid, 256>>>(x, wf_w, wf_b, wi_w, wi_b, wc_w, wc_b, wo_w, wo_b);

    lstm_rec_kernel<<<NB, TPB>>>(wf_w, wi_w, wc_w, wo_w, out);
}